// round 9
// baseline (speedup 1.0000x reference)
#include <cuda_runtime.h>
#include <cuda_fp16.h>
#include <cstdint>

#define BB 2
#define CC 16
#define NN 6912          // 72*96
#define BT 128           // threads per block (4 warps)
#define MW 32            // i rows per warp
#define IT 128           // i rows per block
#define JCH 128          // j chunk in smem
#define JPAD 136         // padded j stride for f2 tile (halfwords)
#define BSTR 24          // padded stride for arg-B tables (halfwords, 48B rows)
#define JSPLIT 18
#define JBLK (NN / JSPLIT)                 // 384 j per block
#define NBLK (JSPLIT * (NN / IT) * BB)     // 1944 pair blocks

#define S1 14.426950408889634f   // 10*log2(e)
#define S2 28.853900817779268f   // 20*log2(e)

// ---------------- scratch ----------------
__device__ __half g_a1h[BB * NN * 16];   // A' table: [Ah(5), Al(5), Ah(5), 0] per i
__device__ __half g_bth[BB * NN * 16];   // B' table (pose-transformed): [Bh,Bh,Bl,0] per j
__device__ __half g_bnh[BB * NN * 16];   // B' table (noisy)
__device__ float  g_f1e[BB * NN * CC];   // f1 normalized*mask, [b][i][c]
__device__ __half g_f2h[BB * CC * NN];   // f2 normalized*mask fp16, [b][c][j]
__device__ double g_acc[BB];
__device__ double g_sm1[BB], g_sm2[BB];
__device__ double g_fns;
__device__ unsigned int g_cnt;           // completion counter (self-resetting)

// ---------------- helpers ----------------
// D pair: 2^t - 2^n on packed f16x2
__device__ __forceinline__ uint32_t dexp2(uint32_t t, uint32_t n) {
    uint32_t rt, rn;
    asm("ex2.approx.f16x2 %0, %1;" : "=r"(rt) : "r"(t));
    asm("ex2.approx.f16x2 %0, %1;" : "=r"(rn) : "r"(n));
    __half2 d = __hsub2(*(__half2*)&rt, *(__half2*)&rn);
    return *(uint32_t*)&d;
}
// f32-accum gram MMA
__device__ __forceinline__ void mma_f16(float* c, const uint32_t* a, const uint32_t* b) {
    asm volatile(
        "mma.sync.aligned.m16n8k16.row.col.f32.f16.f16.f32 "
        "{%0,%1,%2,%3}, {%4,%5,%6,%7}, {%8,%9}, {%0,%1,%2,%3};"
        : "+f"(c[0]), "+f"(c[1]), "+f"(c[2]), "+f"(c[3])
        : "r"(a[0]), "r"(a[1]), "r"(a[2]), "r"(a[3]), "r"(b[0]), "r"(b[1]));
}
// f16-accum arg MMA, C = 0 (distinct zero registers; in/out via "+r")
__device__ __forceinline__ void mma_f16d(uint32_t* d, const uint32_t* a, const uint32_t* b) {
    d[0] = 0u; d[1] = 0u;
    asm volatile(
        "mma.sync.aligned.m16n8k16.row.col.f16.f16.f16.f16 "
        "{%0,%1}, {%2,%3,%4,%5}, {%6,%7}, {%0,%1};"
        : "+r"(d[0]), "+r"(d[1])
        : "r"(a[0]), "r"(a[1]), "r"(a[2]), "r"(a[3]), "r"(b[0]), "r"(b[1]));
}
__device__ __forceinline__ void ldsm4(uint32_t* r, uint32_t addr) {
    asm volatile("ldmatrix.sync.aligned.m8n8.x4.shared.b16 {%0,%1,%2,%3}, [%4];"
        : "=r"(r[0]), "=r"(r[1]), "=r"(r[2]), "=r"(r[3]) : "r"(addr));
}
__device__ __forceinline__ uint32_t smem_u32(const void* p) {
    return (uint32_t)__cvta_generic_to_shared(p);
}
// build [h(5), l(5), h(5), 0]  (A-side k layout)
__device__ __forceinline__ void split5_A(const float* v, __half* o) {
#pragma unroll
    for (int k = 0; k < 5; k++) {
        __half h = __float2half_rn(v[k]);
        o[k] = h; o[10 + k] = h;
        o[5 + k] = __float2half_rn(v[k] - __half2float(h));
    }
    o[15] = __float2half_rn(0.f);
}
// build [h(5), h(5), l(5), 0]  (B-side k layout)
__device__ __forceinline__ void split5_B(const float* v, __half* o) {
#pragma unroll
    for (int k = 0; k < 5; k++) {
        __half h = __float2half_rn(v[k]);
        o[k] = h; o[5 + k] = h;
        o[10 + k] = __float2half_rn(v[k] - __half2float(h));
    }
    o[15] = __float2half_rn(0.f);
}

// ---------------- kernels ----------------
// 2 threads per point: even handles channels 0-7 + A' table; odd 8-15 + B' tables.
__global__ void prep_kernel(const float* __restrict__ f1,
                            const float* __restrict__ f2,
                            const float* __restrict__ d1,
                            const float* __restrict__ d2,
                            const float* __restrict__ pose,
                            const float* __restrict__ yz1) {
    int gid2 = blockIdx.x * blockDim.x + threadIdx.x;  // 2*BB*NN threads
    int gid = gid2 >> 1, half = gid2 & 1;
    int b = gid / NN, i = gid % NN;

    float dd1 = d1[gid], dd2 = d2[gid];
    float m1 = dd1 > 0.f ? 1.f : 0.f;
    float m2 = dd2 > 0.f ? 1.f : 0.f;

    float gx = yz1[i], gy = yz1[NN + i], gz = yz1[2 * NN + i];
    float x1 = gx * dd1, y1 = gy * dd1, z1 = gz * dd1;
    float x2 = gx * dd2, y2 = gy * dd2, z2 = gz * dd2;

    const float* Pm = pose + b * 16;
    float xt = Pm[0]*x2 + Pm[1]*y2 + Pm[2] *z2 + Pm[3];
    float yt = Pm[4]*x2 + Pm[5]*y2 + Pm[6] *z2 + Pm[7];
    float zt = Pm[8]*x2 + Pm[9]*y2 + Pm[10]*z2 + Pm[11];

    float c1 = -S1 * (x1*x1 + y1*y1 + z1*z1);

    if (half == 0) {
        float a5[5] = {S2 * x1, S2 * y1, S2 * z1, c1, 1.f};
        __half o[16];
        split5_A(a5, o);
        *(uint4*)&g_a1h[gid * 16]     = *(uint4*)&o[0];
        *(uint4*)&g_a1h[gid * 16 + 8] = *(uint4*)&o[8];
    } else {
        float bt5[5] = {xt, yt, zt, 1.f, -S1 * (xt*xt + yt*yt + zt*zt)};
        float bn5[5] = {x2, y2, z2, 1.f, -S1 * (x2*x2 + y2*y2 + z2*z2)};
        __half o[16];
        split5_B(bt5, o);
        *(uint4*)&g_bth[gid * 16]     = *(uint4*)&o[0];
        *(uint4*)&g_bth[gid * 16 + 8] = *(uint4*)&o[8];
        split5_B(bn5, o);
        *(uint4*)&g_bnh[gid * 16]     = *(uint4*)&o[0];
        *(uint4*)&g_bnh[gid * 16 + 8] = *(uint4*)&o[8];
    }

    const int c0 = half * 8;
    float a1[8], a2[8];
    float s1 = 0.f, s2 = 0.f;
#pragma unroll
    for (int k = 0; k < 8; k++) {
        float v = f1[(b * CC + c0 + k) * NN + i]; a1[k] = v; s1 += v * v;
        float w = f2[(b * CC + c0 + k) * NN + i]; a2[k] = w; s2 += w * w;
    }
    s1 += __shfl_xor_sync(0xffffffffu, s1, 1);
    s2 += __shfl_xor_sync(0xffffffffu, s2, 1);
    float n1 = sqrtf(s1), n2 = sqrtf(s2);
    float r1 = m1 / (n1 + 1e-8f), r2 = m2 / (n2 + 1e-8f);
#pragma unroll
    for (int k = 0; k < 8; k++) {
        g_f1e[gid * CC + c0 + k] = a1[k] * r1;
        g_f2h[(b * CC + c0 + k) * NN + i] = __float2half_rn(a2[k] * r2);
    }

    // reduction: only even thread contributes (has full norms)
    float sel = (half == 0) ? 1.f : 0.f;
    float vm1 = m1 * sel, vm2 = m2 * sel;
    float vf  = 100.f * (n1 * m1 + n2 * m2) * sel;
#pragma unroll
    for (int o = 16; o > 0; o >>= 1) {
        vm1 += __shfl_down_sync(0xffffffffu, vm1, o);
        vm2 += __shfl_down_sync(0xffffffffu, vm2, o);
        vf  += __shfl_down_sync(0xffffffffu, vf,  o);
    }
    if ((threadIdx.x & 31) == 0) {
        atomicAdd(&g_sm1[b], (double)vm1);
        atomicAdd(&g_sm2[b], (double)vm2);
        atomicAdd(&g_fns,    (double)vf);
    }
}

__global__ __launch_bounds__(BT, 6) void pair_kernel(float* __restrict__ out, int out_size) {
    const int b    = blockIdx.z;
    const int base = b * NN;
    const int ibase = blockIdx.y * IT;
    const int warp = threadIdx.x >> 5, lane = threadIdx.x & 31;
    const int r = lane >> 2, cq = lane & 3;

    __shared__ __half sbT[JCH][BSTR];        // arg-B' (pose) tile
    __shared__ __half sbN[JCH][BSTR];        // arg-B' (noisy)
    __shared__ __half sf [CC][JPAD];         // f2 fp16
    __shared__ float wred[BT / 32];
    __shared__ int is_last;

    // persistent A fragments for the two 16-row i halves
    uint32_t aA[2][4];
#pragma unroll
    for (int rf = 0; rf < 2; rf++) {
        const __half* A0 = g_a1h + (size_t)(base + ibase + warp * MW + rf * 16 + r) * 16;
        const __half* A8 = A0 + 8 * 16;
        aA[rf][0] = *(const uint32_t*)(A0 + 2 * cq);
        aA[rf][1] = *(const uint32_t*)(A8 + 2 * cq);
        aA[rf][2] = *(const uint32_t*)(A0 + 2 * cq + 8);
        aA[rf][3] = *(const uint32_t*)(A8 + 2 * cq + 8);
    }

    // ldmatrix per-lane base addresses: matrix m = lane>>3, row rr = lane&7
    const int lm = lane >> 3, rr = lane & 7;
    const uint32_t adrT0 = smem_u32(&sbT[0][0]) + (((lm >> 1) * 8 + rr) * BSTR + (lm & 1) * 8) * 2;
    const uint32_t adrN0 = smem_u32(&sbN[0][0]) + (((lm >> 1) * 8 + rr) * BSTR + (lm & 1) * 8) * 2;
    const uint32_t adrG0 = smem_u32(&sf[0][0])  + (((lm >> 1) * 8 + rr) * JPAD + (lm & 1) * 8) * 2;

    float acc[2][2][4];
#pragma unroll
    for (int a = 0; a < 2; a++)
#pragma unroll
        for (int n = 0; n < 2; n++)
#pragma unroll
            for (int k = 0; k < 4; k++) acc[a][n][k] = 0.f;

    for (int ch = 0; ch < JBLK / JCH; ch++) {
        const int j0 = blockIdx.x * JBLK + ch * JCH;
        __syncthreads();
        {   // arg-B tables: 32B per j -> padded 48B rows
            int j = threadIdx.x;  // JCH == BT
            const uint4* srcT = (const uint4*)(g_bth + (size_t)(base + j0 + j) * 16);
            const uint4* srcN = (const uint4*)(g_bnh + (size_t)(base + j0 + j) * 16);
            *(uint4*)&sbT[j][0] = srcT[0];
            *(uint4*)&sbT[j][8] = srcT[1];
            *(uint4*)&sbN[j][0] = srcN[0];
            *(uint4*)&sbN[j][8] = srcN[1];
        }
        for (int idx = threadIdx.x; idx < CC * 16; idx += BT) {
            int c = idx >> 4, seg = idx & 15;
            *(uint4*)&sf[c][seg * 8] =
                *(const uint4*)(g_f2h + (size_t)(b * CC + c) * NN + j0 + seg * 8);
        }
        __syncthreads();

        // software-pipelined mainloop: double-buffered fragments
        uint32_t aT = adrT0, aN = adrN0, aG = adrG0;
        uint32_t bT[2][4], bN[2][4], bg[2][4];
        ldsm4(bT[0], aT);  aT += 16 * BSTR * 2;
        ldsm4(bN[0], aN);  aN += 16 * BSTR * 2;
        ldsm4(bg[0], aG);  aG += 16 * 2;
#pragma unroll
        for (int ks = 0; ks < JCH / 16; ks++) {
            const int cur = ks & 1, nx = cur ^ 1;
            if (ks < JCH / 16 - 1) {
                ldsm4(bT[nx], aT);  aT += 16 * BSTR * 2;
                ldsm4(bN[nx], aN);  aN += 16 * BSTR * 2;
                ldsm4(bg[nx], aG);  aG += 16 * 2;
            }
#pragma unroll
            for (int rf = 0; rf < 2; rf++) {
                uint32_t dT0[2], dT1[2], dN0[2], dN1[2];
                mma_f16d(dT0, aA[rf], bT[cur] + 0);
                mma_f16d(dT1, aA[rf], bT[cur] + 2);
                mma_f16d(dN0, aA[rf], bN[cur] + 0);
                mma_f16d(dN1, aA[rf], bN[cur] + 2);
                uint32_t d[4];
                d[0] = dexp2(dT0[0], dN0[0]);
                d[1] = dexp2(dT0[1], dN0[1]);
                d[2] = dexp2(dT1[0], dN1[0]);
                d[3] = dexp2(dT1[1], dN1[1]);
                mma_f16(acc[rf][0], d, bg[cur] + 0);
                mma_f16(acc[rf][1], d, bg[cur] + 2);
            }
        }
    }

    // epilogue: contract C with f1 (normalized, masked)
    float tot = 0.f;
#pragma unroll
    for (int rf = 0; rf < 2; rf++) {
#pragma unroll
        for (int nc = 0; nc < 2; nc++) {
            const float* F0 = g_f1e + (size_t)(base + ibase + warp * MW + rf * 16 + r) * CC + nc * 8 + 2 * cq;
            const float* F1 = F0 + 8 * CC;
            tot += acc[rf][nc][0] * F0[0] + acc[rf][nc][1] * F0[1]
                 + acc[rf][nc][2] * F1[0] + acc[rf][nc][3] * F1[1];
        }
    }
#pragma unroll
    for (int o = 16; o > 0; o >>= 1) tot += __shfl_down_sync(0xffffffffu, tot, o);
    if (lane == 0) wred[warp] = tot;
    __syncthreads();
    if (threadIdx.x == 0) {
        float s = wred[0] + wred[1] + wred[2] + wred[3];
        atomicAdd(&g_acc[b], (double)s);
        __threadfence();
        unsigned int t = atomicAdd(&g_cnt, 1u);
        is_last = (t == NBLK - 1) ? 1 : 0;
    }
    __syncthreads();

    if (is_last) {
        if (threadIdx.x == 0) {
            __threadfence();
            double total = 0.0;
            for (int bb = 0; bb < BB; bb++)
                total += -g_acc[bb] / (g_sm1[bb] * g_sm2[bb]);
            if (out_size > 0) out[0] = (float)total;
            if (out_size > 1) out[1] = (float)total;
            if (out_size > 2) out[2] = (float)g_fns;
            for (int bb = 0; bb < BB; bb++) { g_acc[bb] = 0.0; g_sm1[bb] = 0.0; g_sm2[bb] = 0.0; }
            g_fns = 0.0;
            g_cnt = 0u;
        }
        for (int idx = threadIdx.x + 3; idx < out_size; idx += BT) out[idx] = 0.f;
    }
}

extern "C" void kernel_launch(void* const* d_in, const int* in_sizes, int n_in,
                              void* d_out, int out_size) {
    const float* f1   = (const float*)d_in[0];
    const float* f2   = (const float*)d_in[1];
    const float* d1   = (const float*)d_in[2];
    const float* d2   = (const float*)d_in[3];
    const float* pose = (const float*)d_in[4];
    const float* yz1  = (const float*)d_in[7];
    float* out = (float*)d_out;

    prep_kernel<<<(2 * BB * NN) / 256, 256>>>(f1, f2, d1, d2, pose, yz1);
    pair_kernel<<<dim3(JSPLIT, NN / IT, BB), BT>>>(out, out_size);
}

// round 10
// speedup vs baseline: 1.3115x; 1.3115x over previous
#include <cuda_runtime.h>
#include <cuda_fp16.h>
#include <cstdint>

#define BB 2
#define CC 16
#define NN 6912          // 72*96
#define BT 128           // threads per block (4 warps)
#define MW 32            // i rows per warp
#define IT 128           // i rows per block
#define JCH 128          // j chunk in smem
#define JPAD 136         // padded j stride for f2 tile (halfwords)
#define BSTR 24          // padded stride for arg-B tables (halfwords, 48B rows)
#define JSPLIT 9
#define JBLK (NN / JSPLIT)                 // 768 j per block (6 chunks)
#define NBLK (JSPLIT * (NN / IT) * BB)     // 972 pair blocks -> single wave @8/SM

#define S1 14.426950408889634f   // 10*log2(e)
#define S2 28.853900817779268f   // 20*log2(e)

// ---------------- scratch ----------------
__device__ __half g_a1h[BB * NN * 16];   // A' table: [Ah(5), Al(5), Ah(5), 0] per i
__device__ __half g_bth[BB * NN * 16];   // B' table (pose-transformed): [Bh,Bh,Bl,0] per j
__device__ __half g_bnh[BB * NN * 16];   // B' table (noisy)
__device__ float  g_f1e[BB * NN * CC];   // f1 normalized*mask, [b][i][c]
__device__ __half g_f2h[BB * CC * NN];   // f2 normalized*mask fp16, [b][c][j]
__device__ double g_acc[BB];
__device__ double g_sm1[BB], g_sm2[BB];
__device__ double g_fns;
__device__ unsigned int g_cnt;           // completion counter (self-resetting)

// ---------------- helpers ----------------
// D pair: 2^t - 2^n on packed f16x2
__device__ __forceinline__ uint32_t dexp2(uint32_t t, uint32_t n) {
    uint32_t rt, rn;
    asm("ex2.approx.f16x2 %0, %1;" : "=r"(rt) : "r"(t));
    asm("ex2.approx.f16x2 %0, %1;" : "=r"(rn) : "r"(n));
    __half2 d = __hsub2(*(__half2*)&rt, *(__half2*)&rn);
    return *(uint32_t*)&d;
}
// f32-accum gram MMA
__device__ __forceinline__ void mma_f16(float* c, const uint32_t* a, const uint32_t* b) {
    asm volatile(
        "mma.sync.aligned.m16n8k16.row.col.f32.f16.f16.f32 "
        "{%0,%1,%2,%3}, {%4,%5,%6,%7}, {%8,%9}, {%0,%1,%2,%3};"
        : "+f"(c[0]), "+f"(c[1]), "+f"(c[2]), "+f"(c[3])
        : "r"(a[0]), "r"(a[1]), "r"(a[2]), "r"(a[3]), "r"(b[0]), "r"(b[1]));
}
// f16-accum arg MMA, C = 0 (distinct zero registers; in/out via "+r")
__device__ __forceinline__ void mma_f16d(uint32_t* d, const uint32_t* a, const uint32_t* b) {
    d[0] = 0u; d[1] = 0u;
    asm volatile(
        "mma.sync.aligned.m16n8k16.row.col.f16.f16.f16.f16 "
        "{%0,%1}, {%2,%3,%4,%5}, {%6,%7}, {%0,%1};"
        : "+r"(d[0]), "+r"(d[1])
        : "r"(a[0]), "r"(a[1]), "r"(a[2]), "r"(a[3]), "r"(b[0]), "r"(b[1]));
}
__device__ __forceinline__ void ldsm4(uint32_t* r, uint32_t addr) {
    asm volatile("ldmatrix.sync.aligned.m8n8.x4.shared.b16 {%0,%1,%2,%3}, [%4];"
        : "=r"(r[0]), "=r"(r[1]), "=r"(r[2]), "=r"(r[3]) : "r"(addr));
}
__device__ __forceinline__ uint32_t smem_u32(const void* p) {
    return (uint32_t)__cvta_generic_to_shared(p);
}
// build [h(5), l(5), h(5), 0]  (A-side k layout)
__device__ __forceinline__ void split5_A(const float* v, __half* o) {
#pragma unroll
    for (int k = 0; k < 5; k++) {
        __half h = __float2half_rn(v[k]);
        o[k] = h; o[10 + k] = h;
        o[5 + k] = __float2half_rn(v[k] - __half2float(h));
    }
    o[15] = __float2half_rn(0.f);
}
// build [h(5), h(5), l(5), 0]  (B-side k layout)
__device__ __forceinline__ void split5_B(const float* v, __half* o) {
#pragma unroll
    for (int k = 0; k < 5; k++) {
        __half h = __float2half_rn(v[k]);
        o[k] = h; o[5 + k] = h;
        o[10 + k] = __float2half_rn(v[k] - __half2float(h));
    }
    o[15] = __float2half_rn(0.f);
}

// ---------------- kernels ----------------
// 2 threads per point: even handles channels 0-7 + A' table; odd 8-15 + B' tables.
__global__ void prep_kernel(const float* __restrict__ f1,
                            const float* __restrict__ f2,
                            const float* __restrict__ d1,
                            const float* __restrict__ d2,
                            const float* __restrict__ pose,
                            const float* __restrict__ yz1) {
    int gid2 = blockIdx.x * blockDim.x + threadIdx.x;  // 2*BB*NN threads
    int gid = gid2 >> 1, half = gid2 & 1;
    int b = gid / NN, i = gid % NN;

    float dd1 = d1[gid], dd2 = d2[gid];
    float m1 = dd1 > 0.f ? 1.f : 0.f;
    float m2 = dd2 > 0.f ? 1.f : 0.f;

    float gx = yz1[i], gy = yz1[NN + i], gz = yz1[2 * NN + i];
    float x1 = gx * dd1, y1 = gy * dd1, z1 = gz * dd1;
    float x2 = gx * dd2, y2 = gy * dd2, z2 = gz * dd2;

    const float* Pm = pose + b * 16;
    float xt = Pm[0]*x2 + Pm[1]*y2 + Pm[2] *z2 + Pm[3];
    float yt = Pm[4]*x2 + Pm[5]*y2 + Pm[6] *z2 + Pm[7];
    float zt = Pm[8]*x2 + Pm[9]*y2 + Pm[10]*z2 + Pm[11];

    float c1 = -S1 * (x1*x1 + y1*y1 + z1*z1);

    if (half == 0) {
        float a5[5] = {S2 * x1, S2 * y1, S2 * z1, c1, 1.f};
        __half o[16];
        split5_A(a5, o);
        *(uint4*)&g_a1h[gid * 16]     = *(uint4*)&o[0];
        *(uint4*)&g_a1h[gid * 16 + 8] = *(uint4*)&o[8];
    } else {
        float bt5[5] = {xt, yt, zt, 1.f, -S1 * (xt*xt + yt*yt + zt*zt)};
        float bn5[5] = {x2, y2, z2, 1.f, -S1 * (x2*x2 + y2*y2 + z2*z2)};
        __half o[16];
        split5_B(bt5, o);
        *(uint4*)&g_bth[gid * 16]     = *(uint4*)&o[0];
        *(uint4*)&g_bth[gid * 16 + 8] = *(uint4*)&o[8];
        split5_B(bn5, o);
        *(uint4*)&g_bnh[gid * 16]     = *(uint4*)&o[0];
        *(uint4*)&g_bnh[gid * 16 + 8] = *(uint4*)&o[8];
    }

    const int c0 = half * 8;
    float a1[8], a2[8];
    float s1 = 0.f, s2 = 0.f;
#pragma unroll
    for (int k = 0; k < 8; k++) {
        float v = f1[(b * CC + c0 + k) * NN + i]; a1[k] = v; s1 += v * v;
        float w = f2[(b * CC + c0 + k) * NN + i]; a2[k] = w; s2 += w * w;
    }
    s1 += __shfl_xor_sync(0xffffffffu, s1, 1);
    s2 += __shfl_xor_sync(0xffffffffu, s2, 1);
    float n1 = sqrtf(s1), n2 = sqrtf(s2);
    float r1 = m1 / (n1 + 1e-8f), r2 = m2 / (n2 + 1e-8f);
#pragma unroll
    for (int k = 0; k < 8; k++) {
        g_f1e[gid * CC + c0 + k] = a1[k] * r1;
        g_f2h[(b * CC + c0 + k) * NN + i] = __float2half_rn(a2[k] * r2);
    }

    // reduction: only even thread contributes (has full norms)
    float sel = (half == 0) ? 1.f : 0.f;
    float vm1 = m1 * sel, vm2 = m2 * sel;
    float vf  = 100.f * (n1 * m1 + n2 * m2) * sel;
#pragma unroll
    for (int o = 16; o > 0; o >>= 1) {
        vm1 += __shfl_down_sync(0xffffffffu, vm1, o);
        vm2 += __shfl_down_sync(0xffffffffu, vm2, o);
        vf  += __shfl_down_sync(0xffffffffu, vf,  o);
    }
    if ((threadIdx.x & 31) == 0) {
        atomicAdd(&g_sm1[b], (double)vm1);
        atomicAdd(&g_sm2[b], (double)vm2);
        atomicAdd(&g_fns,    (double)vf);
    }
}

__global__ __launch_bounds__(BT, 8) void pair_kernel(float* __restrict__ out, int out_size) {
    const int b    = blockIdx.z;
    const int base = b * NN;
    const int ibase = blockIdx.y * IT;
    const int warp = threadIdx.x >> 5, lane = threadIdx.x & 31;
    const int r = lane >> 2, cq = lane & 3;

    __shared__ __half sbT[JCH][BSTR];        // arg-B' (pose) tile
    __shared__ __half sbN[JCH][BSTR];        // arg-B' (noisy)
    __shared__ __half sf [CC][JPAD];         // f2 fp16
    __shared__ float wred[BT / 32];
    __shared__ int is_last;

    // persistent A fragments for the two 16-row i halves
    uint32_t aA[2][4];
#pragma unroll
    for (int rf = 0; rf < 2; rf++) {
        const __half* A0 = g_a1h + (size_t)(base + ibase + warp * MW + rf * 16 + r) * 16;
        const __half* A8 = A0 + 8 * 16;
        aA[rf][0] = *(const uint32_t*)(A0 + 2 * cq);
        aA[rf][1] = *(const uint32_t*)(A8 + 2 * cq);
        aA[rf][2] = *(const uint32_t*)(A0 + 2 * cq + 8);
        aA[rf][3] = *(const uint32_t*)(A8 + 2 * cq + 8);
    }

    // ldmatrix per-lane base addresses: matrix m = lane>>3, row rr = lane&7
    const int lm = lane >> 3, rr = lane & 7;
    const uint32_t adrT0 = smem_u32(&sbT[0][0]) + (((lm >> 1) * 8 + rr) * BSTR + (lm & 1) * 8) * 2;
    const uint32_t adrN0 = smem_u32(&sbN[0][0]) + (((lm >> 1) * 8 + rr) * BSTR + (lm & 1) * 8) * 2;
    const uint32_t adrG0 = smem_u32(&sf[0][0])  + (((lm >> 1) * 8 + rr) * JPAD + (lm & 1) * 8) * 2;

    float acc[2][2][4];
#pragma unroll
    for (int a = 0; a < 2; a++)
#pragma unroll
        for (int n = 0; n < 2; n++)
#pragma unroll
            for (int k = 0; k < 4; k++) acc[a][n][k] = 0.f;

    for (int ch = 0; ch < JBLK / JCH; ch++) {
        const int j0 = blockIdx.x * JBLK + ch * JCH;
        __syncthreads();
        {   // arg-B tables: 32B per j -> padded 48B rows
            int j = threadIdx.x;  // JCH == BT
            const uint4* srcT = (const uint4*)(g_bth + (size_t)(base + j0 + j) * 16);
            const uint4* srcN = (const uint4*)(g_bnh + (size_t)(base + j0 + j) * 16);
            *(uint4*)&sbT[j][0] = srcT[0];
            *(uint4*)&sbT[j][8] = srcT[1];
            *(uint4*)&sbN[j][0] = srcN[0];
            *(uint4*)&sbN[j][8] = srcN[1];
        }
        for (int idx = threadIdx.x; idx < CC * 16; idx += BT) {
            int c = idx >> 4, seg = idx & 15;
            *(uint4*)&sf[c][seg * 8] =
                *(const uint4*)(g_f2h + (size_t)(b * CC + c) * NN + j0 + seg * 8);
        }
        __syncthreads();

        uint32_t aT = adrT0, aN = adrN0, aG = adrG0;
#pragma unroll 4
        for (int ks = 0; ks < JCH / 16; ks++) {
            uint32_t bT[4], bN[4], bg[4];
            ldsm4(bT, aT);  aT += 16 * BSTR * 2;
            ldsm4(bN, aN);  aN += 16 * BSTR * 2;
            ldsm4(bg, aG);  aG += 16 * 2;
#pragma unroll
            for (int rf = 0; rf < 2; rf++) {
                uint32_t dT0[2], dT1[2], dN0[2], dN1[2];
                mma_f16d(dT0, aA[rf], bT + 0);
                mma_f16d(dT1, aA[rf], bT + 2);
                mma_f16d(dN0, aA[rf], bN + 0);
                mma_f16d(dN1, aA[rf], bN + 2);
                uint32_t d[4];
                d[0] = dexp2(dT0[0], dN0[0]);
                d[1] = dexp2(dT0[1], dN0[1]);
                d[2] = dexp2(dT1[0], dN1[0]);
                d[3] = dexp2(dT1[1], dN1[1]);
                mma_f16(acc[rf][0], d, bg + 0);
                mma_f16(acc[rf][1], d, bg + 2);
            }
        }
    }

    // epilogue: contract C with f1 (normalized, masked)
    float tot = 0.f;
#pragma unroll
    for (int rf = 0; rf < 2; rf++) {
#pragma unroll
        for (int nc = 0; nc < 2; nc++) {
            const float* F0 = g_f1e + (size_t)(base + ibase + warp * MW + rf * 16 + r) * CC + nc * 8 + 2 * cq;
            const float* F1 = F0 + 8 * CC;
            tot += acc[rf][nc][0] * F0[0] + acc[rf][nc][1] * F0[1]
                 + acc[rf][nc][2] * F1[0] + acc[rf][nc][3] * F1[1];
        }
    }
#pragma unroll
    for (int o = 16; o > 0; o >>= 1) tot += __shfl_down_sync(0xffffffffu, tot, o);
    if (lane == 0) wred[warp] = tot;
    __syncthreads();
    if (threadIdx.x == 0) {
        float s = wred[0] + wred[1] + wred[2] + wred[3];
        atomicAdd(&g_acc[b], (double)s);
        __threadfence();
        unsigned int t = atomicAdd(&g_cnt, 1u);
        is_last = (t == NBLK - 1) ? 1 : 0;
    }
    __syncthreads();

    if (is_last) {
        if (threadIdx.x == 0) {
            __threadfence();
            double total = 0.0;
            for (int bb = 0; bb < BB; bb++)
                total += -g_acc[bb] / (g_sm1[bb] * g_sm2[bb]);
            if (out_size > 0) out[0] = (float)total;
            if (out_size > 1) out[1] = (float)total;
            if (out_size > 2) out[2] = (float)g_fns;
            for (int bb = 0; bb < BB; bb++) { g_acc[bb] = 0.0; g_sm1[bb] = 0.0; g_sm2[bb] = 0.0; }
            g_fns = 0.0;
            g_cnt = 0u;
        }
        for (int idx = threadIdx.x + 3; idx < out_size; idx += BT) out[idx] = 0.f;
    }
}

extern "C" void kernel_launch(void* const* d_in, const int* in_sizes, int n_in,
                              void* d_out, int out_size) {
    const float* f1   = (const float*)d_in[0];
    const float* f2   = (const float*)d_in[1];
    const float* d1   = (const float*)d_in[2];
    const float* d2   = (const float*)d_in[3];
    const float* pose = (const float*)d_in[4];
    const float* yz1  = (const float*)d_in[7];
    float* out = (float*)d_out;

    prep_kernel<<<(2 * BB * NN) / 256, 256>>>(f1, f2, d1, d2, pose, yz1);
    pair_kernel<<<dim3(JSPLIT, NN / IT, BB), BT>>>(out, out_size);
}

// round 11
// speedup vs baseline: 1.4396x; 1.0977x over previous
#include <cuda_runtime.h>
#include <cuda_fp16.h>
#include <cstdint>

#define BB 2
#define CC 16
#define NN 6912          // 72*96
#define BT 128           // threads per block (4 warps)
#define MW 32            // i rows per warp
#define IT 128           // i rows per block
#define JCH 128          // j chunk in smem (== per-block j tile)
#define JPAD 136         // padded j stride for f2 tile (halfwords)
#define BSTR 24          // padded stride for arg-B tables (halfwords, 48B rows)
#define JSPLIT 54        // NN/JCH: one chunk per block
#define NBLK (JSPLIT * (NN / IT) * BB)     // 5832 pair blocks -> ~5 full waves

#define S1 14.426950408889634f   // 10*log2(e)
#define S2 28.853900817779268f   // 20*log2(e)

// ---------------- scratch ----------------
__device__ __half g_a1h[BB * NN * 16];   // A' table: [Ah(5), Al(5), Ah(5), 0] per i
__device__ __half g_bth[BB * NN * 16];   // B' table (pose-transformed): [Bh,Bh,Bl,0] per j
__device__ __half g_bnh[BB * NN * 16];   // B' table (noisy)
__device__ float  g_f1e[BB * NN * CC];   // f1 normalized*mask, [b][i][c]
__device__ __half g_f2h[BB * CC * NN];   // f2 normalized*mask fp16, [b][c][j]
__device__ double g_acc[BB];
__device__ double g_sm1[BB], g_sm2[BB];
__device__ double g_fns;
__device__ unsigned int g_cnt;           // completion counter (self-resetting)

// ---------------- helpers ----------------
__device__ __forceinline__ uint32_t dexp2(uint32_t t, uint32_t n) {
    uint32_t rt, rn;
    asm("ex2.approx.f16x2 %0, %1;" : "=r"(rt) : "r"(t));
    asm("ex2.approx.f16x2 %0, %1;" : "=r"(rn) : "r"(n));
    __half2 d = __hsub2(*(__half2*)&rt, *(__half2*)&rn);
    return *(uint32_t*)&d;
}
__device__ __forceinline__ void mma_f16(float* c, const uint32_t* a, const uint32_t* b) {
    asm volatile(
        "mma.sync.aligned.m16n8k16.row.col.f32.f16.f16.f32 "
        "{%0,%1,%2,%3}, {%4,%5,%6,%7}, {%8,%9}, {%0,%1,%2,%3};"
        : "+f"(c[0]), "+f"(c[1]), "+f"(c[2]), "+f"(c[3])
        : "r"(a[0]), "r"(a[1]), "r"(a[2]), "r"(a[3]), "r"(b[0]), "r"(b[1]));
}
__device__ __forceinline__ void mma_f16d(uint32_t* d, const uint32_t* a, const uint32_t* b) {
    d[0] = 0u; d[1] = 0u;
    asm volatile(
        "mma.sync.aligned.m16n8k16.row.col.f16.f16.f16.f16 "
        "{%0,%1}, {%2,%3,%4,%5}, {%6,%7}, {%0,%1};"
        : "+r"(d[0]), "+r"(d[1])
        : "r"(a[0]), "r"(a[1]), "r"(a[2]), "r"(a[3]), "r"(b[0]), "r"(b[1]));
}
__device__ __forceinline__ void ldsm4(uint32_t* r, uint32_t addr) {
    asm volatile("ldmatrix.sync.aligned.m8n8.x4.shared.b16 {%0,%1,%2,%3}, [%4];"
        : "=r"(r[0]), "=r"(r[1]), "=r"(r[2]), "=r"(r[3]) : "r"(addr));
}
__device__ __forceinline__ uint32_t smem_u32(const void* p) {
    return (uint32_t)__cvta_generic_to_shared(p);
}
__device__ __forceinline__ void split5_A(const float* v, __half* o) {
#pragma unroll
    for (int k = 0; k < 5; k++) {
        __half h = __float2half_rn(v[k]);
        o[k] = h; o[10 + k] = h;
        o[5 + k] = __float2half_rn(v[k] - __half2float(h));
    }
    o[15] = __float2half_rn(0.f);
}
__device__ __forceinline__ void split5_B(const float* v, __half* o) {
#pragma unroll
    for (int k = 0; k < 5; k++) {
        __half h = __float2half_rn(v[k]);
        o[k] = h; o[5 + k] = h;
        o[10 + k] = __float2half_rn(v[k] - __half2float(h));
    }
    o[15] = __float2half_rn(0.f);
}

// ---------------- kernels ----------------
// 256-thread blocks; tid<128 -> channels 0-7 + A' table, tid>=128 -> 8-15 + B' tables.
// i stays lane-contiguous -> fully coalesced feature access.
__global__ void prep_kernel(const float* __restrict__ f1,
                            const float* __restrict__ f2,
                            const float* __restrict__ d1,
                            const float* __restrict__ d2,
                            const float* __restrict__ pose,
                            const float* __restrict__ yz1) {
    const int tid  = threadIdx.x;
    const int half = tid >> 7;                    // warp-uniform
    const int p    = blockIdx.x * 128 + (tid & 127);   // point in [0, BB*NN)
    const int b = p / NN, i = p % NN;

    __shared__ float s1buf[256], s2buf[256];

    float dd1 = d1[p], dd2 = d2[p];
    float m1 = dd1 > 0.f ? 1.f : 0.f;
    float m2 = dd2 > 0.f ? 1.f : 0.f;

    float gx = yz1[i], gy = yz1[NN + i], gz = yz1[2 * NN + i];
    float x1 = gx * dd1, y1 = gy * dd1, z1 = gz * dd1;
    float x2 = gx * dd2, y2 = gy * dd2, z2 = gz * dd2;

    const float* Pm = pose + b * 16;
    float xt = Pm[0]*x2 + Pm[1]*y2 + Pm[2] *z2 + Pm[3];
    float yt = Pm[4]*x2 + Pm[5]*y2 + Pm[6] *z2 + Pm[7];
    float zt = Pm[8]*x2 + Pm[9]*y2 + Pm[10]*z2 + Pm[11];

    float c1 = -S1 * (x1*x1 + y1*y1 + z1*z1);

    if (half == 0) {
        float a5[5] = {S2 * x1, S2 * y1, S2 * z1, c1, 1.f};
        __half o[16];
        split5_A(a5, o);
        *(uint4*)&g_a1h[p * 16]     = *(uint4*)&o[0];
        *(uint4*)&g_a1h[p * 16 + 8] = *(uint4*)&o[8];
    } else {
        float bt5[5] = {xt, yt, zt, 1.f, -S1 * (xt*xt + yt*yt + zt*zt)};
        float bn5[5] = {x2, y2, z2, 1.f, -S1 * (x2*x2 + y2*y2 + z2*z2)};
        __half o[16];
        split5_B(bt5, o);
        *(uint4*)&g_bth[p * 16]     = *(uint4*)&o[0];
        *(uint4*)&g_bth[p * 16 + 8] = *(uint4*)&o[8];
        split5_B(bn5, o);
        *(uint4*)&g_bnh[p * 16]     = *(uint4*)&o[0];
        *(uint4*)&g_bnh[p * 16 + 8] = *(uint4*)&o[8];
    }

    const int c0 = half * 8;
    float a1[8], a2[8];
    float s1 = 0.f, s2 = 0.f;
#pragma unroll
    for (int k = 0; k < 8; k++) {
        float v = f1[(b * CC + c0 + k) * NN + i]; a1[k] = v; s1 += v * v;
        float w = f2[(b * CC + c0 + k) * NN + i]; a2[k] = w; s2 += w * w;
    }
    s1buf[tid] = s1; s2buf[tid] = s2;
    __syncthreads();
    s1 += s1buf[tid ^ 128];
    s2 += s2buf[tid ^ 128];
    float n1 = sqrtf(s1), n2 = sqrtf(s2);
    float r1 = m1 / (n1 + 1e-8f), r2 = m2 / (n2 + 1e-8f);
#pragma unroll
    for (int k = 0; k < 8; k++) {
        g_f1e[p * CC + c0 + k] = a1[k] * r1;
        g_f2h[(b * CC + c0 + k) * NN + i] = __float2half_rn(a2[k] * r2);
    }

    if (half == 0) {   // half-0 warps have full norms; b is warp-uniform
        float vm1 = m1, vm2 = m2, vf = 100.f * (n1 * m1 + n2 * m2);
#pragma unroll
        for (int o = 16; o > 0; o >>= 1) {
            vm1 += __shfl_down_sync(0xffffffffu, vm1, o);
            vm2 += __shfl_down_sync(0xffffffffu, vm2, o);
            vf  += __shfl_down_sync(0xffffffffu, vf,  o);
        }
        if ((tid & 31) == 0) {
            atomicAdd(&g_sm1[b], (double)vm1);
            atomicAdd(&g_sm2[b], (double)vm2);
            atomicAdd(&g_fns,    (double)vf);
        }
    }
}

__global__ __launch_bounds__(BT, 8) void pair_kernel(float* __restrict__ out, int out_size) {
    const int b    = blockIdx.z;
    const int base = b * NN;
    const int ibase = blockIdx.y * IT;
    const int warp = threadIdx.x >> 5, lane = threadIdx.x & 31;
    const int r = lane >> 2, cq = lane & 3;

    __shared__ __half sbT[JCH][BSTR];        // arg-B' (pose) tile
    __shared__ __half sbN[JCH][BSTR];        // arg-B' (noisy)
    __shared__ __half sf [CC][JPAD];         // f2 fp16
    __shared__ float wred[BT / 32];
    __shared__ int is_last;

    // persistent A fragments for the two 16-row i halves
    uint32_t aA[2][4];
#pragma unroll
    for (int rf = 0; rf < 2; rf++) {
        const __half* A0 = g_a1h + (size_t)(base + ibase + warp * MW + rf * 16 + r) * 16;
        const __half* A8 = A0 + 8 * 16;
        aA[rf][0] = *(const uint32_t*)(A0 + 2 * cq);
        aA[rf][1] = *(const uint32_t*)(A8 + 2 * cq);
        aA[rf][2] = *(const uint32_t*)(A0 + 2 * cq + 8);
        aA[rf][3] = *(const uint32_t*)(A8 + 2 * cq + 8);
    }

    // ldmatrix per-lane base addresses: matrix m = lane>>3, row rr = lane&7
    const int lm = lane >> 3, rr = lane & 7;
    const uint32_t adrT0 = smem_u32(&sbT[0][0]) + (((lm >> 1) * 8 + rr) * BSTR + (lm & 1) * 8) * 2;
    const uint32_t adrN0 = smem_u32(&sbN[0][0]) + (((lm >> 1) * 8 + rr) * BSTR + (lm & 1) * 8) * 2;
    const uint32_t adrG0 = smem_u32(&sf[0][0])  + (((lm >> 1) * 8 + rr) * JPAD + (lm & 1) * 8) * 2;

    float acc[2][2][4];
#pragma unroll
    for (int a = 0; a < 2; a++)
#pragma unroll
        for (int n = 0; n < 2; n++)
#pragma unroll
            for (int k = 0; k < 4; k++) acc[a][n][k] = 0.f;

    // single j chunk per block
    const int j0 = blockIdx.x * JCH;
    {   // arg-B tables: 32B per j -> padded 48B rows
        int j = threadIdx.x;  // JCH == BT
        const uint4* srcT = (const uint4*)(g_bth + (size_t)(base + j0 + j) * 16);
        const uint4* srcN = (const uint4*)(g_bnh + (size_t)(base + j0 + j) * 16);
        *(uint4*)&sbT[j][0] = srcT[0];
        *(uint4*)&sbT[j][8] = srcT[1];
        *(uint4*)&sbN[j][0] = srcN[0];
        *(uint4*)&sbN[j][8] = srcN[1];
    }
    for (int idx = threadIdx.x; idx < CC * 16; idx += BT) {
        int c = idx >> 4, seg = idx & 15;
        *(uint4*)&sf[c][seg * 8] =
            *(const uint4*)(g_f2h + (size_t)(b * CC + c) * NN + j0 + seg * 8);
    }
    __syncthreads();

    uint32_t aT = adrT0, aN = adrN0, aG = adrG0;
#pragma unroll 4
    for (int ks = 0; ks < JCH / 16; ks++) {
        uint32_t bT[4], bN[4], bg[4];
        ldsm4(bT, aT);  aT += 16 * BSTR * 2;
        ldsm4(bN, aN);  aN += 16 * BSTR * 2;
        ldsm4(bg, aG);  aG += 16 * 2;
#pragma unroll
        for (int rf = 0; rf < 2; rf++) {
            uint32_t dT0[2], dT1[2], dN0[2], dN1[2];
            mma_f16d(dT0, aA[rf], bT + 0);
            mma_f16d(dT1, aA[rf], bT + 2);
            mma_f16d(dN0, aA[rf], bN + 0);
            mma_f16d(dN1, aA[rf], bN + 2);
            uint32_t d[4];
            d[0] = dexp2(dT0[0], dN0[0]);
            d[1] = dexp2(dT0[1], dN0[1]);
            d[2] = dexp2(dT1[0], dN1[0]);
            d[3] = dexp2(dT1[1], dN1[1]);
            mma_f16(acc[rf][0], d, bg + 0);
            mma_f16(acc[rf][1], d, bg + 2);
        }
    }

    // epilogue: contract C with f1 (normalized, masked)
    float tot = 0.f;
#pragma unroll
    for (int rf = 0; rf < 2; rf++) {
#pragma unroll
        for (int nc = 0; nc < 2; nc++) {
            const float* F0 = g_f1e + (size_t)(base + ibase + warp * MW + rf * 16 + r) * CC + nc * 8 + 2 * cq;
            const float* F1 = F0 + 8 * CC;
            tot += acc[rf][nc][0] * F0[0] + acc[rf][nc][1] * F0[1]
                 + acc[rf][nc][2] * F1[0] + acc[rf][nc][3] * F1[1];
        }
    }
#pragma unroll
    for (int o = 16; o > 0; o >>= 1) tot += __shfl_down_sync(0xffffffffu, tot, o);
    if (lane == 0) wred[warp] = tot;
    __syncthreads();
    if (threadIdx.x == 0) {
        float s = wred[0] + wred[1] + wred[2] + wred[3];
        atomicAdd(&g_acc[b], (double)s);
        __threadfence();
        unsigned int t = atomicAdd(&g_cnt, 1u);
        is_last = (t == NBLK - 1) ? 1 : 0;
    }
    __syncthreads();

    if (is_last) {
        if (threadIdx.x == 0) {
            __threadfence();
            double total = 0.0;
            for (int bb = 0; bb < BB; bb++)
                total += -g_acc[bb] / (g_sm1[bb] * g_sm2[bb]);
            if (out_size > 0) out[0] = (float)total;
            if (out_size > 1) out[1] = (float)total;
            if (out_size > 2) out[2] = (float)g_fns;
            for (int bb = 0; bb < BB; bb++) { g_acc[bb] = 0.0; g_sm1[bb] = 0.0; g_sm2[bb] = 0.0; }
            g_fns = 0.0;
            g_cnt = 0u;
        }
        for (int idx = threadIdx.x + 3; idx < out_size; idx += BT) out[idx] = 0.f;
    }
}

extern "C" void kernel_launch(void* const* d_in, const int* in_sizes, int n_in,
                              void* d_out, int out_size) {
    const float* f1   = (const float*)d_in[0];
    const float* f2   = (const float*)d_in[1];
    const float* d1   = (const float*)d_in[2];
    const float* d2   = (const float*)d_in[3];
    const float* pose = (const float*)d_in[4];
    const float* yz1  = (const float*)d_in[7];
    float* out = (float*)d_out;

    prep_kernel<<<(2 * BB * NN) / 256, 256>>>(f1, f2, d1, d2, pose, yz1);
    pair_kernel<<<dim3(JSPLIT, NN / IT, BB), BT>>>(out, out_size);
}